// round 15
// baseline (speedup 1.0000x reference)
#include <cuda_runtime.h>
#include <cuda_fp16.h>

#define CANVAS 1024
#define NSH 64
#define TEXN 512
#define QDIM 513                 // tap-origin index range 0..512 (tex coord -1..511)
#define VXDIM 514                // x entries: 0..513 (second access reaches qx+1=513)
#define VBW 129                  // morton blocks per row: ceil(516/4)
#define VBH 257                  // morton block rows: ceil(514/2)
#define VTE (VBW * VBH * 8)      // entries per texture
#define T_EPS 1e-4f

// Column-pair table: V[qy][qx] = { texel(yi, xi), texel(yi+1, xi) } as fp16
// RGBA pairs {rgTop, baTop, rgBot, baBot}, where yi=qy-1, xi=qx-1.
// A bilinear sample at origin (xi,yi) reads V[qy][qx] and V[qy][qx+1] —
// adjacent entries; with Morton 4x2 blocking both usually share a 128B line.
// OOB texels are zero (matches reference zero-fill).
__device__ uint4 g_texV[4 * VTE];   // ~17 MB scratch

__device__ __forceinline__ int voff(int qy, int qx) {
    return ((((qy >> 1) * VBW + (qx >> 2)) << 3) | ((qy & 1) << 2) | (qx & 3));
}

// Per-shape transform/color record (compacted into smem per tile).
struct __align__(16) ShapeXfm {
    float tx, ty, m00, m01;
    float m10, m11, r, g;
    float b; int texoff; float pad0, pad1;
};

// ---------------------------------------------------------------------------
// Kernel 1: build the column-pair fp16 table (Morton 4x2 swizzled).
// grid: (513 qy-rows, 4 tex), block 256 sweeps qx 0..513.
// ---------------------------------------------------------------------------
__global__ __launch_bounds__(256) void build_tex_kernel(const float* __restrict__ tex) {
    int t  = blockIdx.y;
    int qy = blockIdx.x;                   // 0..512
    int yi = qy - 1;                       // -1..511
    const int NPIX = TEXN * TEXN;
    const float* base = tex + (size_t)t * 4 * NPIX;
    uint4* tab = g_texV + t * VTE;

    bool topok_y = (unsigned)yi < (unsigned)TEXN;
    bool botok_y = (unsigned)(yi + 1) < (unsigned)TEXN;

    for (int qx = threadIdx.x; qx < VXDIM; qx += 256) {
        int xi = qx - 1;                   // -1..512
        bool xok = (unsigned)xi < (unsigned)TEXN;

        float top[4] = {0.f, 0.f, 0.f, 0.f};
        float bot[4] = {0.f, 0.f, 0.f, 0.f};
        if (xok) {
            if (topok_y) {
                int off = yi * TEXN + xi;
                #pragma unroll
                for (int ch = 0; ch < 4; ch++) top[ch] = __ldg(base + ch * NPIX + off);
            }
            if (botok_y) {
                int off = (yi + 1) * TEXN + xi;
                #pragma unroll
                for (int ch = 0; ch < 4; ch++) bot[ch] = __ldg(base + ch * NPIX + off);
            }
        }

        __half2 h[4];
        h[0] = __floats2half2_rn(top[0], top[1]);   // rg top
        h[1] = __floats2half2_rn(top[2], top[3]);   // ba top
        h[2] = __floats2half2_rn(bot[0], bot[1]);   // rg bot
        h[3] = __floats2half2_rn(bot[2], bot[3]);   // ba bot

        tab[voff(qy, qx)] = *reinterpret_cast<uint4*>(&h[0]);
    }
}

// One bilinear sample + composite step. No-op if lane saturated or outside.
// tb = per-shape table base (g_texV + texoff), hoisted by the caller.
__device__ __forceinline__ void sample_composite(
    const uint4* __restrict__ tb, float cr, float cg, float cb,
    float fu, float fv,
    float& Cr, float& Cg, float& Cb, float& T)
{
    int qx = __float2int_rd(fu);    // valid 0..512
    int qy = __float2int_rd(fv);
    // single fused early-out: saturated OR outside
    bool act = (T > T_EPS) &
               ((unsigned)qx < (unsigned)QDIM) &
               ((unsigned)qy < (unsigned)QDIM);
    if (!act) return;

    float wx = fu - (float)qx;
    float wy = fv - (float)qy;

    int oL = voff(qy, qx);
    int oR = oL + (((qx & 3) == 3) ? 5 : 1);   // incremental Morton step in x

    uint4 eL = __ldg(tb + oL);        // left column pair
    uint4 eR = __ldg(tb + oR);        // right column pair

    __half2 rgTL = *reinterpret_cast<const __half2*>(&eL.x);
    __half2 baTL = *reinterpret_cast<const __half2*>(&eL.y);
    __half2 rgBL = *reinterpret_cast<const __half2*>(&eL.z);
    __half2 baBL = *reinterpret_cast<const __half2*>(&eL.w);
    __half2 rgTR = *reinterpret_cast<const __half2*>(&eR.x);
    __half2 baTR = *reinterpret_cast<const __half2*>(&eR.y);
    __half2 rgBR = *reinterpret_cast<const __half2*>(&eR.z);
    __half2 baBR = *reinterpret_cast<const __half2*>(&eR.w);

    __half2 wx2 = __float2half2_rn(wx);
    __half2 wy2 = __float2half2_rn(wy);

    // lerp within each column in y, then across columns in x
    __half2 rgL = __hfma2(wy2, __hsub2(rgBL, rgTL), rgTL);
    __half2 baL = __hfma2(wy2, __hsub2(baBL, baTL), baTL);
    __half2 rgR = __hfma2(wy2, __hsub2(rgBR, rgTR), rgTR);
    __half2 baR = __hfma2(wy2, __hsub2(baBR, baTR), baTR);
    __half2 rg  = __hfma2(wx2, __hsub2(rgR, rgL), rgL);
    __half2 ba  = __hfma2(wx2, __hsub2(baR, baL), baL);

    float2 rgf = __half22float2(rg);
    float2 baf = __half22float2(ba);

    float Ta = T * baf.y;           // T * alpha
    Cr = fmaf(Ta, rgf.x * cr, Cr);
    Cg = fmaf(Ta, rgf.y * cg, Cg);
    Cb = fmaf(Ta, baf.x * cb, Cb);
    T  = T - Ta;                    // T *= (1 - a)
}

// ---------------------------------------------------------------------------
// Kernel 2: render. TWO pixels per thread (vertical pair); warp = 8x8 pixel
// block; block = 32x16 tile. Per-tile shape compaction + per-warp bbox cull,
// reverse compositing with transmittance early-exit, fp16 bilerp.
// ---------------------------------------------------------------------------
__global__ __launch_bounds__(256) void render_kernel(const int* __restrict__ st,
                                                     const float* __restrict__ params,
                                                     float* __restrict__ out) {
    __shared__ ShapeXfm sxf[NSH];     // compacted, order-preserving
    __shared__ float4   sbox[NSH];    // compacted bboxes (for warp-level cull)
    __shared__ int s_cnt0;
    __shared__ int s_nlive;

    int tid = threadIdx.x;            // 0..255 flat

    // tile bounds (pixel centers), tile = 32x16
    float tX0 = (float)(blockIdx.x * 32) + 0.5f;
    float tX1 = tX0 + 31.0f;
    float tY0 = (float)(blockIdx.y * 16) + 0.5f;
    float tY1 = tY0 + 15.0f;

    // --- per-tile shape prep + compaction (first 2 warps) ---
    bool pass = false;
    ShapeXfm xf;
    float4 bbox;
    if (tid < NSH) {
        const float* p = params + tid * 9;
        float tx = p[0] * (float)CANVAS;
        float ty = p[1] * (float)CANVAS;
        float W  = (float)CANVAS * (0.05f + 0.95f * p[2]);
        float H  = (float)CANVAS * (0.05f + 0.95f * p[3]);
        float as = p[4], ac = p[5];
        float nrm = sqrtf(as * as + ac * ac) + 1e-8f;
        float c = ac / nrm, s = as / nrm;
        float fx = (float)TEXN / W;
        float fy = (float)TEXN / H;

        xf.tx = tx; xf.ty = ty;
        xf.m00 =  c * fx;  xf.m01 = s * fx;
        xf.m10 = -s * fy;  xf.m11 = c * fy;
        xf.r = p[6]; xf.g = p[7]; xf.b = p[8];
        xf.texoff = st[tid] * VTE;
        xf.pad0 = xf.pad1 = 0.f;

        float uh = 0.5f * W * (1.0f + 2.0f / TEXN) + 2.0f;
        float vh = 0.5f * H * (1.0f + 2.0f / TEXN) + 2.0f;
        float ex = fabsf(c) * uh + fabsf(s) * vh;
        float ey = fabsf(s) * uh + fabsf(c) * vh;
        bbox = make_float4(tx - ex, tx + ex, ty - ey, ty + ey);
        pass = !(tX1 < bbox.x || tX0 > bbox.y || tY1 < bbox.z || tY0 > bbox.w);
    }

    unsigned mask = 0;
    int pos = 0;
    if (tid < NSH) {
        mask = __ballot_sync(0xffffffffu, pass);
        pos = __popc(mask & ((1u << (tid & 31)) - 1u));
        if (tid == 0) s_cnt0 = __popc(mask);
    }
    __syncthreads();
    if (tid < NSH) {
        int base = (tid < 32) ? 0 : s_cnt0;
        if (pass) { sxf[base + pos] = xf; sbox[base + pos] = bbox; }
        if (tid == 32) s_nlive = s_cnt0 + __popc(mask);
    }
    __syncthreads();

    int nlive = s_nlive;

    // warp -> 8x8 pixel block; thread -> vertical pixel pair
    int lane = tid & 31;
    int warp = tid >> 5;              // 0..7
    int lx = lane & 7;                // 0..7
    int lyt = lane >> 3;              // 0..3 -> rows 2*lyt, 2*lyt+1
    int bx0 = blockIdx.x * 32 + (warp & 3) * 8;
    int by0 = blockIdx.y * 16 + (warp >> 2) * 8;
    int x  = bx0 + lx;
    int y0 = by0 + lyt * 2;
    float px  = (float)x + 0.5f;
    float py0 = (float)y0 + 0.5f;

    // warp block bounds (pixel centers) — warp-uniform 8x8
    float wX0 = (float)bx0 + 0.5f, wX1 = wX0 + 7.0f;
    float wY0 = (float)by0 + 0.5f, wY1 = wY0 + 7.0f;

    // Reverse compositing per pixel: out = C + T * canvas0(=1)
    float Cr0 = 0.f, Cg0 = 0.f, Cb0 = 0.f, T0 = 1.f;
    float Cr1 = 0.f, Cg1 = 0.f, Cb1 = 0.f, T1 = 1.f;

    for (int k = nlive - 1; k >= 0; k--) {
        if (__all_sync(0xffffffffu, (T0 <= T_EPS) && (T1 <= T_EPS))) break;

        // warp-uniform 8x8 bbox cull
        float4 bb = sbox[k];
        if (wX1 < bb.x || wX0 > bb.y || wY1 < bb.z || wY0 > bb.w)
            continue;

        const ShapeXfm rec = sxf[k];
        const uint4* tb = g_texV + rec.texoff;   // hoisted per-shape base
        float dx = px  - rec.tx;
        float dy = py0 - rec.ty;
        float fu0 = fmaf(rec.m00, dx, fmaf(rec.m01, dy, 256.5f));
        float fv0 = fmaf(rec.m10, dx, fmaf(rec.m11, dy, 256.5f));
        float fu1 = fu0 + rec.m01;     // +1 in canvas y
        float fv1 = fv0 + rec.m11;

        sample_composite(tb, rec.r, rec.g, rec.b, fu0, fv0, Cr0, Cg0, Cb0, T0);
        sample_composite(tb, rec.r, rec.g, rec.b, fu1, fv1, Cr1, Cg1, Cb1, T1);
    }

    int o = y0 * CANVAS + x;
    out[o] = Cr0 + T0;
    out[CANVAS * CANVAS + o] = Cg0 + T0;
    out[2 * CANVAS * CANVAS + o] = Cb0 + T0;
    o += CANVAS;
    out[o] = Cr1 + T1;
    out[CANVAS * CANVAS + o] = Cg1 + T1;
    out[2 * CANVAS * CANVAS + o] = Cb1 + T1;
}

// ---------------------------------------------------------------------------
extern "C" void kernel_launch(void* const* d_in, const int* in_sizes, int n_in,
                              void* d_out, int out_size) {
    const int*   shape_type = (const int*)d_in[0];
    const float* params     = (const float*)d_in[1];
    const float* textures   = (const float*)d_in[2];
    float* out = (float*)d_out;

    dim3 bgrid(QDIM, 4);
    build_tex_kernel<<<bgrid, 256>>>(textures);

    dim3 blk(256);
    dim3 grd(CANVAS / 32, CANVAS / 16);
    render_kernel<<<grd, blk>>>(shape_type, params, out);
}

// round 16
// speedup vs baseline: 1.0006x; 1.0006x over previous
#include <cuda_runtime.h>
#include <cuda_fp16.h>

#define CANVAS 1024
#define NSH 64
#define TEXN 512
#define QDIM 513                 // tap-origin index range 0..512 (tex coord -1..511)
#define VXDIM 514                // x entries: 0..513 (right access reaches qx+1=513)
#define VROW (VXDIM * 2)         // entries per qy-pair row = 1028
#define VPAIRS 257               // qy pairs: ceil(513/2)
#define VTE (VPAIRS * VROW)      // entries per texture
#define T_EPS 3e-4f

// Column-pair table: V[qy][qx] = { texel(yi, xi), texel(yi+1, xi) } as fp16
// RGBA pairs {rgTop, baTop, rgBot, baBot}, where yi=qy-1, xi=qx-1.
// Layout: entry index = (qy>>1)*VROW + 2*qx + (qy&1). A 128B line holds 8
// consecutive entries = 4 consecutive qx x 2 qy — IDENTICAL line geometry to
// the previous Morton 4x2 swizzle, but the index is 4 cheap ops and the
// right neighbor (qx+1) is a constant +2. OOB texels are zero.
__device__ uint4 g_texV[4 * VTE];   // ~16.9 MB scratch

__device__ __forceinline__ int voff(int qy, int qx) {
    return (qy >> 1) * VROW + (qx << 1) + (qy & 1);
}

// Per-shape transform/color record (compacted into smem per tile).
struct __align__(16) ShapeXfm {
    float tx, ty, m00, m01;
    float m10, m11, r, g;
    float b; int texoff; float pad0, pad1;
};

// ---------------------------------------------------------------------------
// Kernel 1: build the column-pair fp16 table.
// grid: (513 qy-rows, 4 tex), block 256 sweeps qx 0..513.
// ---------------------------------------------------------------------------
__global__ __launch_bounds__(256) void build_tex_kernel(const float* __restrict__ tex) {
    int t  = blockIdx.y;
    int qy = blockIdx.x;                   // 0..512
    int yi = qy - 1;                       // -1..511
    const int NPIX = TEXN * TEXN;
    const float* base = tex + (size_t)t * 4 * NPIX;
    uint4* tab = g_texV + t * VTE;

    bool topok_y = (unsigned)yi < (unsigned)TEXN;
    bool botok_y = (unsigned)(yi + 1) < (unsigned)TEXN;

    for (int qx = threadIdx.x; qx < VXDIM; qx += 256) {
        int xi = qx - 1;                   // -1..512
        bool xok = (unsigned)xi < (unsigned)TEXN;

        float top[4] = {0.f, 0.f, 0.f, 0.f};
        float bot[4] = {0.f, 0.f, 0.f, 0.f};
        if (xok) {
            if (topok_y) {
                int off = yi * TEXN + xi;
                #pragma unroll
                for (int ch = 0; ch < 4; ch++) top[ch] = __ldg(base + ch * NPIX + off);
            }
            if (botok_y) {
                int off = (yi + 1) * TEXN + xi;
                #pragma unroll
                for (int ch = 0; ch < 4; ch++) bot[ch] = __ldg(base + ch * NPIX + off);
            }
        }

        __half2 h[4];
        h[0] = __floats2half2_rn(top[0], top[1]);   // rg top
        h[1] = __floats2half2_rn(top[2], top[3]);   // ba top
        h[2] = __floats2half2_rn(bot[0], bot[1]);   // rg bot
        h[3] = __floats2half2_rn(bot[2], bot[3]);   // ba bot

        tab[voff(qy, qx)] = *reinterpret_cast<uint4*>(&h[0]);
    }
}

// One bilinear sample + composite step. No-op if lane saturated or outside.
// tb = per-shape table base (g_texV + texoff), hoisted by the caller.
__device__ __forceinline__ void sample_composite(
    const uint4* __restrict__ tb, float cr, float cg, float cb,
    float fu, float fv,
    float& Cr, float& Cg, float& Cb, float& T)
{
    int qx = __float2int_rd(fu);    // valid 0..512
    int qy = __float2int_rd(fv);
    // single fused early-out: saturated OR outside
    bool act = (T > T_EPS) &
               ((unsigned)qx < (unsigned)QDIM) &
               ((unsigned)qy < (unsigned)QDIM);
    if (!act) return;

    float wx = fu - (float)qx;
    float wy = fv - (float)qy;

    int oL = voff(qy, qx);
    uint4 eL = __ldg(tb + oL);        // left column pair
    uint4 eR = __ldg(tb + oL + 2);    // right column pair (qx+1 -> +2, constant)

    __half2 rgTL = *reinterpret_cast<const __half2*>(&eL.x);
    __half2 baTL = *reinterpret_cast<const __half2*>(&eL.y);
    __half2 rgBL = *reinterpret_cast<const __half2*>(&eL.z);
    __half2 baBL = *reinterpret_cast<const __half2*>(&eL.w);
    __half2 rgTR = *reinterpret_cast<const __half2*>(&eR.x);
    __half2 baTR = *reinterpret_cast<const __half2*>(&eR.y);
    __half2 rgBR = *reinterpret_cast<const __half2*>(&eR.z);
    __half2 baBR = *reinterpret_cast<const __half2*>(&eR.w);

    __half2 wx2 = __float2half2_rn(wx);
    __half2 wy2 = __float2half2_rn(wy);

    // lerp within each column in y, then across columns in x
    __half2 rgL = __hfma2(wy2, __hsub2(rgBL, rgTL), rgTL);
    __half2 baL = __hfma2(wy2, __hsub2(baBL, baTL), baTL);
    __half2 rgR = __hfma2(wy2, __hsub2(rgBR, rgTR), rgTR);
    __half2 baR = __hfma2(wy2, __hsub2(baBR, baTR), baTR);
    __half2 rg  = __hfma2(wx2, __hsub2(rgR, rgL), rgL);
    __half2 ba  = __hfma2(wx2, __hsub2(baR, baL), baL);

    float2 rgf = __half22float2(rg);
    float2 baf = __half22float2(ba);

    float Ta = T * baf.y;           // T * alpha
    Cr = fmaf(Ta, rgf.x * cr, Cr);
    Cg = fmaf(Ta, rgf.y * cg, Cg);
    Cb = fmaf(Ta, baf.x * cb, Cb);
    T  = T - Ta;                    // T *= (1 - a)
}

// ---------------------------------------------------------------------------
// Kernel 2: render. TWO pixels per thread (vertical pair); warp = 8x8 pixel
// block; block = 32x16 tile. Per-tile shape compaction + per-warp bbox cull,
// reverse compositing with transmittance early-exit, fp16 bilerp.
// ---------------------------------------------------------------------------
__global__ __launch_bounds__(256) void render_kernel(const int* __restrict__ st,
                                                     const float* __restrict__ params,
                                                     float* __restrict__ out) {
    __shared__ ShapeXfm sxf[NSH];     // compacted, order-preserving
    __shared__ float4   sbox[NSH];    // compacted bboxes (for warp-level cull)
    __shared__ int s_cnt0;
    __shared__ int s_nlive;

    int tid = threadIdx.x;            // 0..255 flat

    // tile bounds (pixel centers), tile = 32x16
    float tX0 = (float)(blockIdx.x * 32) + 0.5f;
    float tX1 = tX0 + 31.0f;
    float tY0 = (float)(blockIdx.y * 16) + 0.5f;
    float tY1 = tY0 + 15.0f;

    // --- per-tile shape prep + compaction (first 2 warps) ---
    bool pass = false;
    ShapeXfm xf;
    float4 bbox;
    if (tid < NSH) {
        const float* p = params + tid * 9;
        float tx = p[0] * (float)CANVAS;
        float ty = p[1] * (float)CANVAS;
        float W  = (float)CANVAS * (0.05f + 0.95f * p[2]);
        float H  = (float)CANVAS * (0.05f + 0.95f * p[3]);
        float as = p[4], ac = p[5];
        float nrm = sqrtf(as * as + ac * ac) + 1e-8f;
        float c = ac / nrm, s = as / nrm;
        float fx = (float)TEXN / W;
        float fy = (float)TEXN / H;

        xf.tx = tx; xf.ty = ty;
        xf.m00 =  c * fx;  xf.m01 = s * fx;
        xf.m10 = -s * fy;  xf.m11 = c * fy;
        xf.r = p[6]; xf.g = p[7]; xf.b = p[8];
        xf.texoff = st[tid] * VTE;
        xf.pad0 = xf.pad1 = 0.f;

        float uh = 0.5f * W * (1.0f + 2.0f / TEXN) + 2.0f;
        float vh = 0.5f * H * (1.0f + 2.0f / TEXN) + 2.0f;
        float ex = fabsf(c) * uh + fabsf(s) * vh;
        float ey = fabsf(s) * uh + fabsf(c) * vh;
        bbox = make_float4(tx - ex, tx + ex, ty - ey, ty + ey);
        pass = !(tX1 < bbox.x || tX0 > bbox.y || tY1 < bbox.z || tY0 > bbox.w);
    }

    unsigned mask = 0;
    int pos = 0;
    if (tid < NSH) {
        mask = __ballot_sync(0xffffffffu, pass);
        pos = __popc(mask & ((1u << (tid & 31)) - 1u));
        if (tid == 0) s_cnt0 = __popc(mask);
    }
    __syncthreads();
    if (tid < NSH) {
        int base = (tid < 32) ? 0 : s_cnt0;
        if (pass) { sxf[base + pos] = xf; sbox[base + pos] = bbox; }
        if (tid == 32) s_nlive = s_cnt0 + __popc(mask);
    }
    __syncthreads();

    int nlive = s_nlive;

    // warp -> 8x8 pixel block; thread -> vertical pixel pair
    int lane = tid & 31;
    int warp = tid >> 5;              // 0..7
    int lx = lane & 7;                // 0..7
    int lyt = lane >> 3;              // 0..3 -> rows 2*lyt, 2*lyt+1
    int bx0 = blockIdx.x * 32 + (warp & 3) * 8;
    int by0 = blockIdx.y * 16 + (warp >> 2) * 8;
    int x  = bx0 + lx;
    int y0 = by0 + lyt * 2;
    float px  = (float)x + 0.5f;
    float py0 = (float)y0 + 0.5f;

    // warp block bounds (pixel centers) — warp-uniform 8x8
    float wX0 = (float)bx0 + 0.5f, wX1 = wX0 + 7.0f;
    float wY0 = (float)by0 + 0.5f, wY1 = wY0 + 7.0f;

    // Reverse compositing per pixel: out = C + T * canvas0(=1)
    float Cr0 = 0.f, Cg0 = 0.f, Cb0 = 0.f, T0 = 1.f;
    float Cr1 = 0.f, Cg1 = 0.f, Cb1 = 0.f, T1 = 1.f;

    for (int k = nlive - 1; k >= 0; k--) {
        if (__all_sync(0xffffffffu, (T0 <= T_EPS) && (T1 <= T_EPS))) break;

        // warp-uniform 8x8 bbox cull
        float4 bb = sbox[k];
        if (wX1 < bb.x || wX0 > bb.y || wY1 < bb.z || wY0 > bb.w)
            continue;

        const ShapeXfm rec = sxf[k];
        const uint4* tb = g_texV + rec.texoff;   // hoisted per-shape base
        float dx = px  - rec.tx;
        float dy = py0 - rec.ty;
        float fu0 = fmaf(rec.m00, dx, fmaf(rec.m01, dy, 256.5f));
        float fv0 = fmaf(rec.m10, dx, fmaf(rec.m11, dy, 256.5f));
        float fu1 = fu0 + rec.m01;     // +1 in canvas y
        float fv1 = fv0 + rec.m11;

        sample_composite(tb, rec.r, rec.g, rec.b, fu0, fv0, Cr0, Cg0, Cb0, T0);
        sample_composite(tb, rec.r, rec.g, rec.b, fu1, fv1, Cr1, Cg1, Cb1, T1);
    }

    int o = y0 * CANVAS + x;
    out[o] = Cr0 + T0;
    out[CANVAS * CANVAS + o] = Cg0 + T0;
    out[2 * CANVAS * CANVAS + o] = Cb0 + T0;
    o += CANVAS;
    out[o] = Cr1 + T1;
    out[CANVAS * CANVAS + o] = Cg1 + T1;
    out[2 * CANVAS * CANVAS + o] = Cb1 + T1;
}

// ---------------------------------------------------------------------------
extern "C" void kernel_launch(void* const* d_in, const int* in_sizes, int n_in,
                              void* d_out, int out_size) {
    const int*   shape_type = (const int*)d_in[0];
    const float* params     = (const float*)d_in[1];
    const float* textures   = (const float*)d_in[2];
    float* out = (float*)d_out;

    dim3 bgrid(QDIM, 4);
    build_tex_kernel<<<bgrid, 256>>>(textures);

    dim3 blk(256);
    dim3 grd(CANVAS / 32, CANVAS / 16);
    render_kernel<<<grd, blk>>>(shape_type, params, out);
}